// round 1
// baseline (speedup 1.0000x reference)
#include <cuda_runtime.h>
#include <math.h>

#define B_   16
#define N_   1024
#define E_   768
#define H_   12
#define D_   64
#define TOK  (B_ * N_)

// Scratch (no allocations allowed): Q,K,V,attn-out in [b*H+h][n][d] layout.
__device__ float g_Q [(size_t)B_ * H_ * N_ * D_];
__device__ float g_K [(size_t)B_ * H_ * N_ * D_];
__device__ float g_V [(size_t)B_ * H_ * N_ * D_];
__device__ float g_AO[(size_t)B_ * H_ * N_ * D_];

// ---------------------------------------------------------------------------
// GEMM: C[t, o] = sum_k X[t,k] * W[o,k] + b[o], scattered to [b,h,n,d] layout.
// Tile 128x128x8, 256 threads, 8x8 per-thread micro tile.
// ---------------------------------------------------------------------------
__global__ __launch_bounds__(256) void gemm_qkv_kernel(
    const float* __restrict__ X, const float* __restrict__ W,
    const float* __restrict__ bias, float* __restrict__ out)
{
    __shared__ float As[8 * 132];
    __shared__ float Bs[8 * 132];
    const int tid = threadIdx.x;
    const int m0 = blockIdx.x * 128;
    const int n0 = blockIdx.y * 128;
    const int ty = tid >> 4, tx = tid & 15;
    const int lrow = tid >> 1;
    const int lk = (tid & 1) * 4;

    float acc[8][8];
#pragma unroll
    for (int i = 0; i < 8; i++)
#pragma unroll
        for (int j = 0; j < 8; j++) acc[i][j] = 0.0f;

    const float* Ap = X + (size_t)(m0 + lrow) * E_ + lk;
    const float* Bp = W + (size_t)(n0 + lrow) * E_ + lk;

    for (int k0 = 0; k0 < E_; k0 += 8) {
        float4 av = *(const float4*)(Ap + k0);
        float4 bv = *(const float4*)(Bp + k0);
        As[(lk + 0) * 132 + lrow] = av.x;
        As[(lk + 1) * 132 + lrow] = av.y;
        As[(lk + 2) * 132 + lrow] = av.z;
        As[(lk + 3) * 132 + lrow] = av.w;
        Bs[(lk + 0) * 132 + lrow] = bv.x;
        Bs[(lk + 1) * 132 + lrow] = bv.y;
        Bs[(lk + 2) * 132 + lrow] = bv.z;
        Bs[(lk + 3) * 132 + lrow] = bv.w;
        __syncthreads();
#pragma unroll
        for (int k = 0; k < 8; k++) {
            float4 a0 = *(const float4*)&As[k * 132 + ty * 8];
            float4 a1 = *(const float4*)&As[k * 132 + ty * 8 + 4];
            float4 b0 = *(const float4*)&Bs[k * 132 + tx * 8];
            float4 b1 = *(const float4*)&Bs[k * 132 + tx * 8 + 4];
            float a[8] = {a0.x, a0.y, a0.z, a0.w, a1.x, a1.y, a1.z, a1.w};
            float b[8] = {b0.x, b0.y, b0.z, b0.w, b1.x, b1.y, b1.z, b1.w};
#pragma unroll
            for (int i = 0; i < 8; i++)
#pragma unroll
                for (int j = 0; j < 8; j++) acc[i][j] += a[i] * b[j];
        }
        __syncthreads();
    }

#pragma unroll
    for (int i = 0; i < 8; i++) {
        int row = m0 + ty * 8 + i;
        int bb = row >> 10, nn = row & (N_ - 1);
#pragma unroll
        for (int j = 0; j < 8; j++) {
            int col = n0 + tx * 8 + j;
            int h = col >> 6, d = col & 63;
            out[(((size_t)bb * H_ + h) * N_ + nn) * D_ + d] = acc[i][j] + bias[col];
        }
    }
}

// ---------------------------------------------------------------------------
// Output projection: A gathered from [b,h,n,d] layout, C written [t, e].
// ---------------------------------------------------------------------------
__global__ __launch_bounds__(256) void gemm_out_kernel(
    const float* __restrict__ AO, const float* __restrict__ W,
    const float* __restrict__ bias, float* __restrict__ out)
{
    __shared__ float As[8 * 132];
    __shared__ float Bs[8 * 132];
    const int tid = threadIdx.x;
    const int m0 = blockIdx.x * 128;
    const int n0 = blockIdx.y * 128;
    const int ty = tid >> 4, tx = tid & 15;
    const int lrow = tid >> 1;
    const int lk = (tid & 1) * 4;

    float acc[8][8];
#pragma unroll
    for (int i = 0; i < 8; i++)
#pragma unroll
        for (int j = 0; j < 8; j++) acc[i][j] = 0.0f;

    const int t = m0 + lrow;
    const int bb = t >> 10, nn = t & (N_ - 1);
    const float* Bp = W + (size_t)(n0 + lrow) * E_ + lk;

    for (int k0 = 0; k0 < E_; k0 += 8) {
        int k = k0 + lk;
        int h = k >> 6, d = k & 63;
        float4 av = *(const float4*)(AO + (((size_t)bb * H_ + h) * N_ + nn) * D_ + d);
        float4 bv = *(const float4*)(Bp + k0);
        As[(lk + 0) * 132 + lrow] = av.x;
        As[(lk + 1) * 132 + lrow] = av.y;
        As[(lk + 2) * 132 + lrow] = av.z;
        As[(lk + 3) * 132 + lrow] = av.w;
        Bs[(lk + 0) * 132 + lrow] = bv.x;
        Bs[(lk + 1) * 132 + lrow] = bv.y;
        Bs[(lk + 2) * 132 + lrow] = bv.z;
        Bs[(lk + 3) * 132 + lrow] = bv.w;
        __syncthreads();
#pragma unroll
        for (int k2 = 0; k2 < 8; k2++) {
            float4 a0 = *(const float4*)&As[k2 * 132 + ty * 8];
            float4 a1 = *(const float4*)&As[k2 * 132 + ty * 8 + 4];
            float4 b0 = *(const float4*)&Bs[k2 * 132 + tx * 8];
            float4 b1 = *(const float4*)&Bs[k2 * 132 + tx * 8 + 4];
            float a[8] = {a0.x, a0.y, a0.z, a0.w, a1.x, a1.y, a1.z, a1.w};
            float b[8] = {b0.x, b0.y, b0.z, b0.w, b1.x, b1.y, b1.z, b1.w};
#pragma unroll
            for (int i = 0; i < 8; i++)
#pragma unroll
                for (int j = 0; j < 8; j++) acc[i][j] += a[i] * b[j];
        }
        __syncthreads();
    }

#pragma unroll
    for (int i = 0; i < 8; i++) {
        int row = m0 + ty * 8 + i;
#pragma unroll
        for (int j = 0; j < 8; j++) {
            int col = n0 + tx * 8 + j;
            out[(size_t)row * E_ + col] = acc[i][j] + bias[col];
        }
    }
}

// ---------------------------------------------------------------------------
// Fused flash attention (fp32): one block = 64 query rows of one (b,h).
// QsT [d][row] stride 64 | KsT/Ps stride 68 | Vs [key][d] stride 64.
// Thread (ty,tx) of 16x16 owns S/O rows ty*4..+3, cols tx*4..+3.
// ---------------------------------------------------------------------------
#define QS_STRIDE 64
#define KS_STRIDE 68
#define VS_STRIDE 64
#define ATTN_SMEM ((64 * QS_STRIDE + 64 * KS_STRIDE + 64 * VS_STRIDE) * 4)

__global__ __launch_bounds__(256) void attn_kernel(
    const float* __restrict__ Q, const float* __restrict__ K,
    const float* __restrict__ V, float* __restrict__ O)
{
    extern __shared__ float sm[];
    float* QsT = sm;                       // 64*64
    float* KsT = sm + 64 * QS_STRIDE;      // 64*68 (reused as Ps)
    float* Vs  = KsT + 64 * KS_STRIDE;     // 64*64

    const int tid = threadIdx.x;
    const int ty = tid >> 4, tx = tid & 15;
    const int bh = blockIdx.y;
    const int q0 = blockIdx.x * 64;
    const float SC = 0.125f;  // 1/sqrt(64)

    const float* Qb = Q + (size_t)bh * N_ * D_;
    const float* Kb = K + (size_t)bh * N_ * D_;
    const float* Vb = V + (size_t)bh * N_ * D_;

    // Load Q tile transposed: QsT[d][row]
#pragma unroll
    for (int it = 0; it < 4; it++) {
        int idx = tid + it * 256;          // float4 index 0..1023
        int row = idx >> 4;
        int d4 = (idx & 15) << 2;
        float4 v = *(const float4*)(Qb + (size_t)(q0 + row) * D_ + d4);
        QsT[(d4 + 0) * QS_STRIDE + row] = v.x;
        QsT[(d4 + 1) * QS_STRIDE + row] = v.y;
        QsT[(d4 + 2) * QS_STRIDE + row] = v.z;
        QsT[(d4 + 3) * QS_STRIDE + row] = v.w;
    }

    float m_[4], l_[4], o_[4][4];
#pragma unroll
    for (int i = 0; i < 4; i++) {
        m_[i] = -INFINITY; l_[i] = 0.0f;
#pragma unroll
        for (int j = 0; j < 4; j++) o_[i][j] = 0.0f;
    }

    for (int kc = 0; kc < N_; kc += 64) {
        __syncthreads();  // prior-iter Ps/Vs reads done (also covers Q-tile stores)
        // Load K chunk transposed into KsT, V chunk natural into Vs.
#pragma unroll
        for (int it = 0; it < 4; it++) {
            int idx = tid + it * 256;
            int row = idx >> 4;
            int d4 = (idx & 15) << 2;
            float4 kv = *(const float4*)(Kb + (size_t)(kc + row) * D_ + d4);
            KsT[(d4 + 0) * KS_STRIDE + row] = kv.x;
            KsT[(d4 + 1) * KS_STRIDE + row] = kv.y;
            KsT[(d4 + 2) * KS_STRIDE + row] = kv.z;
            KsT[(d4 + 3) * KS_STRIDE + row] = kv.w;
            float4 vv = *(const float4*)(Vb + (size_t)(kc + row) * D_ + d4);
            *(float4*)&Vs[row * VS_STRIDE + d4] = vv;
        }
        __syncthreads();

        // S = Q K^T (64 inner d)
        float s[4][4];
#pragma unroll
        for (int i = 0; i < 4; i++)
#pragma unroll
            for (int j = 0; j < 4; j++) s[i][j] = 0.0f;
#pragma unroll 8
        for (int kd = 0; kd < 64; kd++) {
            float4 aq = *(const float4*)&QsT[kd * QS_STRIDE + ty * 4];
            float4 bk = *(const float4*)&KsT[kd * KS_STRIDE + tx * 4];
            float a[4] = {aq.x, aq.y, aq.z, aq.w};
            float b[4] = {bk.x, bk.y, bk.z, bk.w};
#pragma unroll
            for (int i = 0; i < 4; i++)
#pragma unroll
                for (int j = 0; j < 4; j++) s[i][j] += a[i] * b[j];
        }

        // Online softmax (row state replicated across the 16 tx threads)
#pragma unroll
        for (int i = 0; i < 4; i++) {
#pragma unroll
            for (int j = 0; j < 4; j++) s[i][j] *= SC;
            float cm = fmaxf(fmaxf(s[i][0], s[i][1]), fmaxf(s[i][2], s[i][3]));
            cm = fmaxf(cm, __shfl_xor_sync(0xffffffffu, cm, 8));
            cm = fmaxf(cm, __shfl_xor_sync(0xffffffffu, cm, 4));
            cm = fmaxf(cm, __shfl_xor_sync(0xffffffffu, cm, 2));
            cm = fmaxf(cm, __shfl_xor_sync(0xffffffffu, cm, 1));
            float nm = fmaxf(m_[i], cm);
            float corr = __expf(m_[i] - nm);
            float sum = 0.0f;
#pragma unroll
            for (int j = 0; j < 4; j++) {
                float p = __expf(s[i][j] - nm);
                s[i][j] = p;
                sum += p;
            }
            sum += __shfl_xor_sync(0xffffffffu, sum, 8);
            sum += __shfl_xor_sync(0xffffffffu, sum, 4);
            sum += __shfl_xor_sync(0xffffffffu, sum, 2);
            sum += __shfl_xor_sync(0xffffffffu, sum, 1);
            l_[i] = l_[i] * corr + sum;
            m_[i] = nm;
#pragma unroll
            for (int j = 0; j < 4; j++) o_[i][j] *= corr;
        }

        __syncthreads();  // all S reads of KsT done
        // Store P into KsT space as Ps[row][key], stride 68
#pragma unroll
        for (int i = 0; i < 4; i++) {
            *(float4*)&KsT[(ty * 4 + i) * KS_STRIDE + tx * 4] =
                make_float4(s[i][0], s[i][1], s[i][2], s[i][3]);
        }
        __syncthreads();

        // O += P @ V
#pragma unroll 4
        for (int k4 = 0; k4 < 64; k4 += 4) {
            float4 p[4];
#pragma unroll
            for (int i = 0; i < 4; i++)
                p[i] = *(const float4*)&KsT[(ty * 4 + i) * KS_STRIDE + k4];
            float4 v0 = *(const float4*)&Vs[(k4 + 0) * VS_STRIDE + tx * 4];
            float4 v1 = *(const float4*)&Vs[(k4 + 1) * VS_STRIDE + tx * 4];
            float4 v2 = *(const float4*)&Vs[(k4 + 2) * VS_STRIDE + tx * 4];
            float4 v3 = *(const float4*)&Vs[(k4 + 3) * VS_STRIDE + tx * 4];
#pragma unroll
            for (int i = 0; i < 4; i++) {
                o_[i][0] += p[i].x * v0.x + p[i].y * v1.x + p[i].z * v2.x + p[i].w * v3.x;
                o_[i][1] += p[i].x * v0.y + p[i].y * v1.y + p[i].z * v2.y + p[i].w * v3.y;
                o_[i][2] += p[i].x * v0.z + p[i].y * v1.z + p[i].z * v2.z + p[i].w * v3.z;
                o_[i][3] += p[i].x * v0.w + p[i].y * v1.w + p[i].z * v2.w + p[i].w * v3.w;
            }
        }
    }

    // Epilogue: normalize and store
#pragma unroll
    for (int i = 0; i < 4; i++) {
        float inv = 1.0f / l_[i];
        int row = q0 + ty * 4 + i;
        float4 r = make_float4(o_[i][0] * inv, o_[i][1] * inv,
                               o_[i][2] * inv, o_[i][3] * inv);
        *(float4*)&O[((size_t)bh * N_ + row) * D_ + tx * 4] = r;
    }
}

// ---------------------------------------------------------------------------
extern "C" void kernel_launch(void* const* d_in, const int* in_sizes, int n_in,
                              void* d_out, int out_size)
{
    const float* x  = (const float*)d_in[0];
    const float* Wq = (const float*)d_in[1];
    const float* bq = (const float*)d_in[2];
    const float* Wk = (const float*)d_in[3];
    const float* bk = (const float*)d_in[4];
    const float* Wv = (const float*)d_in[5];
    const float* bv = (const float*)d_in[6];
    const float* Wo = (const float*)d_in[7];
    const float* bo = (const float*)d_in[8];
    float* out = (float*)d_out;

    float *Qp, *Kp, *Vp, *AOp;
    cudaGetSymbolAddress((void**)&Qp,  g_Q);
    cudaGetSymbolAddress((void**)&Kp,  g_K);
    cudaGetSymbolAddress((void**)&Vp,  g_V);
    cudaGetSymbolAddress((void**)&AOp, g_AO);

    cudaFuncSetAttribute(attn_kernel,
                         cudaFuncAttributeMaxDynamicSharedMemorySize, ATTN_SMEM);

    dim3 gg(TOK / 128, E_ / 128);
    gemm_qkv_kernel<<<gg, 256>>>(x, Wq, bq, Qp);
    gemm_qkv_kernel<<<gg, 256>>>(x, Wk, bk, Kp);
    gemm_qkv_kernel<<<gg, 256>>>(x, Wv, bv, Vp);

    dim3 ga(N_ / 64, B_ * H_);
    attn_kernel<<<ga, 256, ATTN_SMEM>>>(Qp, Kp, Vp, AOp);

    gemm_out_kernel<<<gg, 256>>>(AOp, Wo, bo, out);
}

// round 3
// speedup vs baseline: 2.3426x; 2.3426x over previous
#include <cuda_runtime.h>
#include <math.h>
#include <cstdint>

#define B_   16
#define N_   1024
#define E_   768
#define H_   12
#define D_   64
#define TOK  (B_ * N_)

// Scratch (no allocations allowed).
__device__ float g_Q [(size_t)B_ * H_ * N_ * D_];   // [b*H+h][n][d]
__device__ float g_K [(size_t)B_ * H_ * N_ * D_];
__device__ float g_V [(size_t)B_ * H_ * N_ * D_];
__device__ float g_AO[(size_t)TOK * E_];            // [b][n][e]

// ---------------------------------------------------------------------------
// helpers
// ---------------------------------------------------------------------------
__device__ __forceinline__ uint32_t tf32b(float x) {
    uint32_t u;
    asm("cvt.rna.tf32.f32 %0, %1;" : "=r"(u) : "f"(x));
    return u;
}
__device__ __forceinline__ float u2f(uint32_t u) { return __uint_as_float(u); }
__device__ __forceinline__ uint32_t f2u(float f) { return __float_as_uint(f); }

__device__ __forceinline__ void mma8(float* c, const uint32_t* a,
                                     uint32_t b0, uint32_t b1) {
    asm volatile(
        "mma.sync.aligned.m16n8k8.row.col.f32.tf32.tf32.f32 "
        "{%0,%1,%2,%3}, {%4,%5,%6,%7}, {%8,%9}, {%0,%1,%2,%3};\n"
        : "+f"(c[0]), "+f"(c[1]), "+f"(c[2]), "+f"(c[3])
        : "r"(a[0]), "r"(a[1]), "r"(a[2]), "r"(a[3]), "r"(b0), "r"(b1));
}

// Fast exp on the FMA pipe (no MUFU).
__device__ __forceinline__ float fexp(float x) {
    x = fmaxf(x, -80.0f);
    float t = x * 1.4426950408889634f;
    float z = t + 12582912.0f;
    int   e = __float_as_int(z);
    float f = t - (z - 12582912.0f);
    float p = 1.3333558e-3f;
    p = fmaf(p, f, 9.6181291e-3f);
    p = fmaf(p, f, 5.5504109e-2f);
    p = fmaf(p, f, 2.4022651e-1f);
    p = fmaf(p, f, 6.9314718e-1f);
    p = fmaf(p, f, 1.0f);
    return __int_as_float(__float_as_int(p) + (e << 23));
}

// ---------------------------------------------------------------------------
// tf32 mma.sync GEMM: C[m,n] = A[m,:] . W[n,:] + bias[n]
// BM=BN=128, BK=32, 256 thr (8 warps as 4x2), warp tile 32x64.
// Smem rows hold 32 k-values, k-pair interleaved within 8-groups
// (pos = (k&~7) + 2*(k&3) + ((k&7)>>2)), rows padded to 40 floats.
// ---------------------------------------------------------------------------
#define GPAD 40
#define GEMM_SMEM (2 * 2 * 128 * GPAD * 4)   // 81920 B

template <bool SCATTER>
__global__ __launch_bounds__(256, 2) void mma_gemm(
    const float* __restrict__ A, const float* __restrict__ W,
    const float* __restrict__ bias, float* __restrict__ C)
{
    extern __shared__ float sm[];
    float* sA = sm;                    // [2][128*GPAD]
    float* sB = sm + 2 * 128 * GPAD;   // [2][128*GPAD]

    const int tid = threadIdx.x;
    const int wid = tid >> 5, lane = tid & 31;
    const int g = lane >> 2, q = lane & 3;
    const int wm = wid >> 1, wn = wid & 1;
    const int m0 = blockIdx.x * 128, n0 = blockIdx.y * 128;

    const int f4 = tid & 7, rl = tid >> 3;           // rows rl + i*32
    const int sbase = (f4 >> 1) * 8 + (f4 & 1);      // interleaved base pos

    float4 ra[4], rb[4];
    float acc[2][8][4];
#pragma unroll
    for (int mi = 0; mi < 2; mi++)
#pragma unroll
        for (int ni = 0; ni < 8; ni++)
#pragma unroll
            for (int r = 0; r < 4; r++) acc[mi][ni][r] = 0.0f;

    auto ldg = [&](int ko) {
#pragma unroll
        for (int i = 0; i < 4; i++) {
            int row = rl + i * 32;
            ra[i] = *(const float4*)(A + (size_t)(m0 + row) * E_ + ko * 32 + f4 * 4);
            rb[i] = *(const float4*)(W + (size_t)(n0 + row) * E_ + ko * 32 + f4 * 4);
        }
    };
    auto sts = [&](int s) {
        float* pa = sA + s * 128 * GPAD;
        float* pb = sB + s * 128 * GPAD;
#pragma unroll
        for (int i = 0; i < 4; i++) {
            int row = rl + i * 32;
            float* da = pa + row * GPAD + sbase;
            da[0] = u2f(tf32b(ra[i].x)); da[2] = u2f(tf32b(ra[i].y));
            da[4] = u2f(tf32b(ra[i].z)); da[6] = u2f(tf32b(ra[i].w));
            float* db = pb + row * GPAD + sbase;
            db[0] = u2f(tf32b(rb[i].x)); db[2] = u2f(tf32b(rb[i].y));
            db[4] = u2f(tf32b(rb[i].z)); db[6] = u2f(tf32b(rb[i].w));
        }
    };

    ldg(0); sts(0); __syncthreads();

    for (int ko = 0; ko < E_ / 32; ko++) {
        int s = ko & 1;
        if (ko < E_ / 32 - 1) ldg(ko + 1);
        const float* pa = sA + s * 128 * GPAD;
        const float* pb = sB + s * 128 * GPAD;
#pragma unroll
        for (int kc = 0; kc < 4; kc++) {
            uint32_t af[2][4];
#pragma unroll
            for (int mi = 0; mi < 2; mi++) {
                float2 lo = *(const float2*)(pa + (wm * 32 + mi * 16 + g) * GPAD + kc * 8 + 2 * q);
                float2 hi = *(const float2*)(pa + (wm * 32 + mi * 16 + g + 8) * GPAD + kc * 8 + 2 * q);
                af[mi][0] = f2u(lo.x); af[mi][1] = f2u(hi.x);
                af[mi][2] = f2u(lo.y); af[mi][3] = f2u(hi.y);
            }
#pragma unroll
            for (int ni = 0; ni < 8; ni++) {
                float2 bv = *(const float2*)(pb + (wn * 64 + ni * 8 + g) * GPAD + kc * 8 + 2 * q);
                uint32_t b0 = f2u(bv.x), b1 = f2u(bv.y);
                mma8(acc[0][ni], af[0], b0, b1);
                mma8(acc[1][ni], af[1], b0, b1);
            }
        }
        if (ko < E_ / 32 - 1) sts((ko + 1) & 1);
        __syncthreads();
    }

    // epilogue
#pragma unroll
    for (int mi = 0; mi < 2; mi++) {
        int r0 = m0 + wm * 32 + mi * 16 + g, r1 = r0 + 8;
#pragma unroll
        for (int ni = 0; ni < 8; ni++) {
            int cb = n0 + wn * 64 + ni * 8;
            int c0 = cb + 2 * q;
            float bx = __ldg(bias + c0), by = __ldg(bias + c0 + 1);
            float2 v0 = make_float2(acc[mi][ni][0] + bx, acc[mi][ni][1] + by);
            float2 v1 = make_float2(acc[mi][ni][2] + bx, acc[mi][ni][3] + by);
            if (SCATTER) {
                int h = cb >> 6, d0 = (cb & 63) + 2 * q;
                int bb0 = r0 >> 10, nn0 = r0 & (N_ - 1);
                int bb1 = r1 >> 10, nn1 = r1 & (N_ - 1);
                *(float2*)(C + (((size_t)bb0 * H_ + h) * N_ + nn0) * D_ + d0) = v0;
                *(float2*)(C + (((size_t)bb1 * H_ + h) * N_ + nn1) * D_ + d0) = v1;
            } else {
                *(float2*)(C + (size_t)r0 * E_ + c0) = v0;
                *(float2*)(C + (size_t)r1 * E_ + c0) = v1;
            }
        }
    }
}

// ---------------------------------------------------------------------------
// Flash attention, tf32 mma.sync for QK^T and P@V.
// Block = 128 q rows of one (b,h); 8 warps, warp = 16 rows x 64 keys.
// Qs [128][68] (d-interleaved), KP [128][68] (K chunk rows 0..63, then P),
// Vs [64][68] (V^T: rows=d, cols=key-interleaved).
// ---------------------------------------------------------------------------
#define APAD 68
#define ATTN_SMEM ((128 + 128 + 64) * APAD * 4)   // 87040 B

__global__ __launch_bounds__(256, 2) void attn_mma(
    const float* __restrict__ Q, const float* __restrict__ K,
    const float* __restrict__ V, float* __restrict__ O)
{
    extern __shared__ float sm[];
    float* Qs = sm;                    // 128*APAD
    float* KP = sm + 128 * APAD;       // 128*APAD
    float* Vs = KP + 128 * APAD;       // 64*APAD

    const int tid = threadIdx.x;
    const int wid = tid >> 5, lane = tid & 31;
    const int g = lane >> 2, q = lane & 3;
    const int bh = blockIdx.y;
    const int q0 = blockIdx.x * 128;

    const float* Qb = Q + (size_t)bh * N_ * D_;
    const float* Kb = K + (size_t)bh * N_ * D_;
    const float* Vb = V + (size_t)bh * N_ * D_;

    // Load Q (scaled by 1/8, exact) into interleaved smem
    {
        int f4 = tid & 15, rl = tid >> 4;
        int sbase = (f4 >> 1) * 8 + (f4 & 1);
#pragma unroll
        for (int i = 0; i < 8; i++) {
            int row = rl + i * 16;
            float4 v = *(const float4*)(Qb + (size_t)(q0 + row) * D_ + f4 * 4);
            float* d = Qs + row * APAD + sbase;
            d[0] = u2f(tf32b(v.x * 0.125f)); d[2] = u2f(tf32b(v.y * 0.125f));
            d[4] = u2f(tf32b(v.z * 0.125f)); d[6] = u2f(tf32b(v.w * 0.125f));
        }
    }
    __syncthreads();

    // Register-resident Q fragments (reused for all 16 key chunks)
    uint32_t qf[8][4];
#pragma unroll
    for (int kc = 0; kc < 8; kc++) {
        float2 lo = *(const float2*)(Qs + (wid * 16 + g) * APAD + kc * 8 + 2 * q);
        float2 hi = *(const float2*)(Qs + (wid * 16 + g + 8) * APAD + kc * 8 + 2 * q);
        qf[kc][0] = f2u(lo.x); qf[kc][1] = f2u(hi.x);
        qf[kc][2] = f2u(lo.y); qf[kc][3] = f2u(hi.y);
    }

    float of[8][4];
#pragma unroll
    for (int ni = 0; ni < 8; ni++)
#pragma unroll
        for (int r = 0; r < 4; r++) of[ni][r] = 0.0f;
    float mA = -INFINITY, mB = -INFINITY, lA = 0.0f, lB = 0.0f;

    for (int ck = 0; ck < N_ / 64; ck++) {
        const float* Kc = Kb + (size_t)ck * 64 * D_;
        const float* Vc = Vb + (size_t)ck * 64 * D_;
        __syncthreads();   // prior P/V reads complete
        // K chunk -> KP rows 0..63 (d-interleaved)
        {
            int f4 = tid & 15, rl = tid >> 4;
            int sbase = (f4 >> 1) * 8 + (f4 & 1);
#pragma unroll
            for (int i = 0; i < 4; i++) {
                int row = rl + i * 16;
                float4 v = *(const float4*)(Kc + (size_t)row * D_ + f4 * 4);
                float* d = KP + row * APAD + sbase;
                d[0] = u2f(tf32b(v.x)); d[2] = u2f(tf32b(v.y));
                d[4] = u2f(tf32b(v.z)); d[6] = u2f(tf32b(v.w));
            }
        }
        // V chunk -> Vs transposed (rows=d, cols=key-interleaved)
        {
            int key = tid & 63, dg = tid >> 6;
            int kp = (key & ~7) + 2 * (key & 3) + ((key & 7) >> 2);
#pragma unroll
            for (int i = 0; i < 4; i++) {
                int d4 = (dg + i * 4) * 4;
                float4 v = *(const float4*)(Vc + (size_t)key * D_ + d4);
                Vs[(d4 + 0) * APAD + kp] = u2f(tf32b(v.x));
                Vs[(d4 + 1) * APAD + kp] = u2f(tf32b(v.y));
                Vs[(d4 + 2) * APAD + kp] = u2f(tf32b(v.z));
                Vs[(d4 + 3) * APAD + kp] = u2f(tf32b(v.w));
            }
        }
        __syncthreads();

        // S = Q K^T
        float sf[8][4];
#pragma unroll
        for (int ni = 0; ni < 8; ni++)
#pragma unroll
            for (int r = 0; r < 4; r++) sf[ni][r] = 0.0f;
#pragma unroll
        for (int kc = 0; kc < 8; kc++) {
#pragma unroll
            for (int ni = 0; ni < 8; ni++) {
                float2 bv = *(const float2*)(KP + (ni * 8 + g) * APAD + kc * 8 + 2 * q);
                mma8(sf[ni], qf[kc], f2u(bv.x), f2u(bv.y));
            }
        }

        // Online softmax (rows rA = wid*16+g, rB = rA+8; lane-quad = one row)
        float mxA = -INFINITY, mxB = -INFINITY;
#pragma unroll
        for (int ni = 0; ni < 8; ni++) {
            mxA = fmaxf(mxA, fmaxf(sf[ni][0], sf[ni][1]));
            mxB = fmaxf(mxB, fmaxf(sf[ni][2], sf[ni][3]));
        }
        mxA = fmaxf(mxA, __shfl_xor_sync(0xffffffffu, mxA, 1));
        mxA = fmaxf(mxA, __shfl_xor_sync(0xffffffffu, mxA, 2));
        mxB = fmaxf(mxB, __shfl_xor_sync(0xffffffffu, mxB, 1));
        mxB = fmaxf(mxB, __shfl_xor_sync(0xffffffffu, mxB, 2));
        float nmA = fmaxf(mA, mxA), nmB = fmaxf(mB, mxB);
        float cA = fexp(mA - nmA), cB = fexp(mB - nmB);
        float suA = 0.0f, suB = 0.0f;
#pragma unroll
        for (int ni = 0; ni < 8; ni++) {
            sf[ni][0] = fexp(sf[ni][0] - nmA);
            sf[ni][1] = fexp(sf[ni][1] - nmA);
            sf[ni][2] = fexp(sf[ni][2] - nmB);
            sf[ni][3] = fexp(sf[ni][3] - nmB);
            suA += sf[ni][0] + sf[ni][1];
            suB += sf[ni][2] + sf[ni][3];
        }
        suA += __shfl_xor_sync(0xffffffffu, suA, 1);
        suA += __shfl_xor_sync(0xffffffffu, suA, 2);
        suB += __shfl_xor_sync(0xffffffffu, suB, 1);
        suB += __shfl_xor_sync(0xffffffffu, suB, 2);
        lA = lA * cA + suA; lB = lB * cB + suB;
        mA = nmA; mB = nmB;
#pragma unroll
        for (int ni = 0; ni < 8; ni++) {
            of[ni][0] *= cA; of[ni][1] *= cA;
            of[ni][2] *= cB; of[ni][3] *= cB;
        }

        __syncthreads();   // all K reads done; KP becomes P
        // Store P (key-interleaved), tf32
        {
            int rA = wid * 16 + g, rB = rA + 8;
            int p0 = 2 * ((2 * q) & 3) + (q >> 1);       // {0,4,1,5}
            int p1 = 2 * ((2 * q + 1) & 3) + (q >> 1);   // {2,6,3,7}
#pragma unroll
            for (int ni = 0; ni < 8; ni++) {
                float* ba = KP + rA * APAD + ni * 8;
                float* bb = KP + rB * APAD + ni * 8;
                ba[p0] = u2f(tf32b(sf[ni][0])); ba[p1] = u2f(tf32b(sf[ni][1]));
                bb[p0] = u2f(tf32b(sf[ni][2])); bb[p1] = u2f(tf32b(sf[ni][3]));
            }
        }
        __syncthreads();

        // O += P @ V
#pragma unroll
        for (int kc = 0; kc < 8; kc++) {
            uint32_t af[4];
            float2 lo = *(const float2*)(KP + (wid * 16 + g) * APAD + kc * 8 + 2 * q);
            float2 hi = *(const float2*)(KP + (wid * 16 + g + 8) * APAD + kc * 8 + 2 * q);
            af[0] = f2u(lo.x); af[1] = f2u(hi.x);
            af[2] = f2u(lo.y); af[3] = f2u(hi.y);
#pragma unroll
            for (int ni = 0; ni < 8; ni++) {
                float2 bv = *(const float2*)(Vs + (ni * 8 + g) * APAD + kc * 8 + 2 * q);
                mma8(of[ni], af, f2u(bv.x), f2u(bv.y));
            }
        }
    }

    // Epilogue -> O in [b, n, E] layout
    const int bb = bh / H_, hh = bh - bb * H_;
    float iA = 1.0f / lA, iB = 1.0f / lB;
    int rA = q0 + wid * 16 + g, rB = rA + 8;
#pragma unroll
    for (int ni = 0; ni < 8; ni++) {
        int d0 = ni * 8 + 2 * q;
        float2 vA = make_float2(of[ni][0] * iA, of[ni][1] * iA);
        float2 vB = make_float2(of[ni][2] * iB, of[ni][3] * iB);
        *(float2*)(O + ((size_t)(bb * N_ + rA)) * E_ + hh * D_ + d0) = vA;
        *(float2*)(O + ((size_t)(bb * N_ + rB)) * E_ + hh * D_ + d0) = vB;
    }
}

// ---------------------------------------------------------------------------
extern "C" void kernel_launch(void* const* d_in, const int* in_sizes, int n_in,
                              void* d_out, int out_size)
{
    const float* x  = (const float*)d_in[0];
    const float* Wq = (const float*)d_in[1];
    const float* bq = (const float*)d_in[2];
    const float* Wk = (const float*)d_in[3];
    const float* bk = (const float*)d_in[4];
    const float* Wv = (const float*)d_in[5];
    const float* bv = (const float*)d_in[6];
    const float* Wo = (const float*)d_in[7];
    const float* bo = (const float*)d_in[8];
    float* out = (float*)d_out;

    float *Qp, *Kp, *Vp, *AOp;
    cudaGetSymbolAddress((void**)&Qp,  g_Q);
    cudaGetSymbolAddress((void**)&Kp,  g_K);
    cudaGetSymbolAddress((void**)&Vp,  g_V);
    cudaGetSymbolAddress((void**)&AOp, g_AO);

    cudaFuncSetAttribute(mma_gemm<true>,
                         cudaFuncAttributeMaxDynamicSharedMemorySize, GEMM_SMEM);
    cudaFuncSetAttribute(mma_gemm<false>,
                         cudaFuncAttributeMaxDynamicSharedMemorySize, GEMM_SMEM);
    cudaFuncSetAttribute(attn_mma,
                         cudaFuncAttributeMaxDynamicSharedMemorySize, ATTN_SMEM);

    dim3 gg(TOK / 128, E_ / 128);
    mma_gemm<true><<<gg, 256, GEMM_SMEM>>>(x, Wq, bq, Qp);
    mma_gemm<true><<<gg, 256, GEMM_SMEM>>>(x, Wk, bk, Kp);
    mma_gemm<true><<<gg, 256, GEMM_SMEM>>>(x, Wv, bv, Vp);

    dim3 ga(N_ / 128, B_ * H_);
    attn_mma<<<ga, 256, ATTN_SMEM>>>(Qp, Kp, Vp, AOp);

    mma_gemm<false><<<gg, 256, GEMM_SMEM>>>(AOp, Wo, bo, out);
}

// round 4
// speedup vs baseline: 3.6775x; 1.5698x over previous
#include <cuda_runtime.h>
#include <math.h>
#include <cstdint>

#define B_   16
#define N_   1024
#define E_   768
#define H_   12
#define D_   64
#define TOK  (B_ * N_)

// Scratch (no allocations allowed).
__device__ float g_Q [(size_t)B_ * H_ * N_ * D_];   // [b*H+h][n][d], tf32-rounded
__device__ float g_K [(size_t)B_ * H_ * N_ * D_];
__device__ float g_V [(size_t)B_ * H_ * N_ * D_];
__device__ float g_AO[(size_t)TOK * E_];            // [b][n][e], tf32-rounded
__device__ float g_Xr[(size_t)TOK * E_];            // tf32-rounded x
__device__ float g_Wr[4][(size_t)E_ * E_];          // tf32-rounded Wq,Wk,Wv,Wo

// ---------------------------------------------------------------------------
// helpers
// ---------------------------------------------------------------------------
__device__ __forceinline__ uint32_t smem_u32(const void* p) {
    uint32_t a;
    asm("{ .reg .u64 t; cvta.to.shared.u64 t, %1; cvt.u32.u64 %0, t; }" : "=r"(a) : "l"(p));
    return a;
}
__device__ __forceinline__ uint32_t tf32b(float x) {
    uint32_t u;
    asm("cvt.rna.tf32.f32 %0, %1;" : "=r"(u) : "f"(x));
    return u;
}
__device__ __forceinline__ float u2f(uint32_t u) { return __uint_as_float(u); }
__device__ __forceinline__ uint32_t f2u(float f) { return __float_as_uint(f); }

__device__ __forceinline__ void mma8(float* c, const uint32_t* a,
                                     uint32_t b0, uint32_t b1) {
    asm volatile(
        "mma.sync.aligned.m16n8k8.row.col.f32.tf32.tf32.f32 "
        "{%0,%1,%2,%3}, {%4,%5,%6,%7}, {%8,%9}, {%0,%1,%2,%3};\n"
        : "+f"(c[0]), "+f"(c[1]), "+f"(c[2]), "+f"(c[3])
        : "r"(a[0]), "r"(a[1]), "r"(a[2]), "r"(a[3]), "r"(b0), "r"(b1));
}

#define CP16(dst, src) \
    asm volatile("cp.async.cg.shared.global [%0], [%1], 16;" :: "r"(dst), "l"(src))
#define CP_COMMIT() asm volatile("cp.async.commit_group;" ::: "memory")
template <int N>
__device__ __forceinline__ void cp_wait() {
    asm volatile("cp.async.wait_group %0;" :: "n"(N) : "memory");
}

// Fast exp on the FMA pipe (no MUFU).
__device__ __forceinline__ float fexp(float x) {
    x = fmaxf(x, -80.0f);
    float t = x * 1.4426950408889634f;
    float z = t + 12582912.0f;
    int   e = __float_as_int(z);
    float f = t - (z - 12582912.0f);
    float p = 1.3333558e-3f;
    p = fmaf(p, f, 9.6181291e-3f);
    p = fmaf(p, f, 5.5504109e-2f);
    p = fmaf(p, f, 2.4022651e-1f);
    p = fmaf(p, f, 6.9314718e-1f);
    p = fmaf(p, f, 1.0f);
    return __int_as_float(__float_as_int(p) + (e << 23));
}

// ---------------------------------------------------------------------------
// tf32 RN rounding prepass
// ---------------------------------------------------------------------------
__global__ __launch_bounds__(256) void round_tf32_kernel(
    const float4* __restrict__ in, float4* __restrict__ out, int n4)
{
    int i = blockIdx.x * blockDim.x + threadIdx.x;
    if (i >= n4) return;
    float4 v = in[i];
    v.x = u2f(tf32b(v.x)); v.y = u2f(tf32b(v.y));
    v.z = u2f(tf32b(v.z)); v.w = u2f(tf32b(v.w));
    out[i] = v;
}

// ---------------------------------------------------------------------------
// tf32 mma.sync GEMM, cp.async 3-stage pipeline.
// BM=BN=128, BK=32 (rows of 32 floats, stride 36 => conflict-free LDS.32).
// QKV=true: fused Q/K/V (grid.y = 18), epilogue rounds + scatters to [b,h,n,d].
// QKV=false: plain C[t,e] = A.W^T + b, no rounding.
// ---------------------------------------------------------------------------
#define GSTG  (256 * 36)                 // floats per stage (A 128x36 + B 128x36)
#define GEMM_SMEM (3 * GSTG * 4)         // 110592 B

template <bool QKV>
__global__ __launch_bounds__(256, 2) void tf32_gemm(
    const float* __restrict__ A, const float* __restrict__ Wbase,
    const float* __restrict__ bp0, const float* __restrict__ bp1,
    const float* __restrict__ bp2,
    float* __restrict__ C0, float* __restrict__ C1, float* __restrict__ C2)
{
    extern __shared__ float sm[];
    const uint32_t sb = smem_u32(sm);
    const int tid = threadIdx.x;
    const int wid = tid >> 5, lane = tid & 31;
    const int g = lane >> 2, q = lane & 3;
    const int wm = wid >> 1, wn = wid & 1;
    const int m0 = blockIdx.x * 128;

    int n0;
    const float* W;
    const float* bias;
    float* C;
    if (QKV) {
        int which = blockIdx.y / 6;
        n0 = (blockIdx.y % 6) * 128;
        W = Wbase + (size_t)which * E_ * E_;
        bias = (which == 0) ? bp0 : (which == 1) ? bp1 : bp2;
        C = (which == 0) ? C0 : (which == 1) ? C1 : C2;
    } else {
        n0 = blockIdx.y * 128;
        W = Wbase; bias = bp0; C = C0;
    }

    auto issue = [&](int ko) {
        uint32_t base = sb + (uint32_t)(ko % 3) * GSTG * 4;
        const float* Ab = A + (size_t)m0 * E_ + ko * 32;
        const float* Wb = W + (size_t)n0 * E_ + ko * 32;
#pragma unroll
        for (int i = 0; i < 4; i++) {
            int c = tid + i * 256;          // 0..1023
            int row = c >> 3, c4 = c & 7;
            CP16(base + (uint32_t)(row * 36 + c4 * 4) * 4,
                 Ab + (size_t)row * E_ + c4 * 4);
            CP16(base + (uint32_t)(128 * 36 + row * 36 + c4 * 4) * 4,
                 Wb + (size_t)row * E_ + c4 * 4);
        }
    };

    float acc[2][8][4];
#pragma unroll
    for (int mi = 0; mi < 2; mi++)
#pragma unroll
        for (int ni = 0; ni < 8; ni++)
#pragma unroll
            for (int r = 0; r < 4; r++) acc[mi][ni][r] = 0.0f;

    issue(0); CP_COMMIT();
    issue(1); CP_COMMIT();

    for (int ko = 0; ko < E_ / 32; ko++) {
        if (ko + 2 < E_ / 32) issue(ko + 2);
        CP_COMMIT();
        cp_wait<2>();
        __syncthreads();
        const float* pa = sm + (ko % 3) * GSTG;
        const float* pb = pa + 128 * 36;
#pragma unroll
        for (int kc = 0; kc < 4; kc++) {
            uint32_t af[2][4];
#pragma unroll
            for (int mi = 0; mi < 2; mi++) {
                const float* r0 = pa + (wm * 32 + mi * 16 + g) * 36 + kc * 8;
                const float* r1 = r0 + 8 * 36;
                af[mi][0] = f2u(r0[q]);     af[mi][1] = f2u(r1[q]);
                af[mi][2] = f2u(r0[q + 4]); af[mi][3] = f2u(r1[q + 4]);
            }
#pragma unroll
            for (int ni = 0; ni < 8; ni++) {
                const float* rb = pb + (wn * 64 + ni * 8 + g) * 36 + kc * 8;
                uint32_t b0 = f2u(rb[q]), b1 = f2u(rb[q + 4]);
                mma8(acc[0][ni], af[0], b0, b1);
                mma8(acc[1][ni], af[1], b0, b1);
            }
        }
        __syncthreads();
    }

    // epilogue
#pragma unroll
    for (int mi = 0; mi < 2; mi++) {
        int r0 = m0 + wm * 32 + mi * 16 + g, r1 = r0 + 8;
#pragma unroll
        for (int ni = 0; ni < 8; ni++) {
            int cb = (QKV ? n0 : n0) + wn * 64 + ni * 8;
            int c0 = cb + 2 * q;
            float bx = __ldg(bias + c0), by = __ldg(bias + c0 + 1);
            float v00 = acc[mi][ni][0] + bx, v01 = acc[mi][ni][1] + by;
            float v10 = acc[mi][ni][2] + bx, v11 = acc[mi][ni][3] + by;
            if (QKV) {
                v00 = u2f(tf32b(v00)); v01 = u2f(tf32b(v01));
                v10 = u2f(tf32b(v10)); v11 = u2f(tf32b(v11));
                int h = cb >> 6, d0 = (cb & 63) + 2 * q;
                int bb0 = r0 >> 10, nn0 = r0 & (N_ - 1);
                int bb1 = r1 >> 10, nn1 = r1 & (N_ - 1);
                *(float2*)(C + (((size_t)bb0 * H_ + h) * N_ + nn0) * D_ + d0) =
                    make_float2(v00, v01);
                *(float2*)(C + (((size_t)bb1 * H_ + h) * N_ + nn1) * D_ + d0) =
                    make_float2(v10, v11);
            } else {
                *(float2*)(C + (size_t)r0 * E_ + c0) = make_float2(v00, v01);
                *(float2*)(C + (size_t)r1 * E_ + c0) = make_float2(v10, v11);
            }
        }
    }
}

// ---------------------------------------------------------------------------
// Flash attention: cp.async double-buffered K/V, P kept in registers
// (shuffle-transposed S fragments feed the PV mma directly).
// Q [128][68], K 2x[64][68] (rows=key, cols=d), V 2x[64][72] (rows=key, cols=d).
// Warp = 16 q-rows x 64 keys. All fragment loads are conflict-free LDS.32.
// ---------------------------------------------------------------------------
#define AQ_OFF 0
#define AK_OFF (128 * 68)                 // 8704
#define AV_OFF (AK_OFF + 2 * 64 * 68)     // 17408
#define ATTN_FLOATS (AV_OFF + 2 * 64 * 72)
#define ATTN_SMEM (ATTN_FLOATS * 4)       // 106496 B

__global__ __launch_bounds__(256, 2) void attn_mma(
    const float* __restrict__ Q, const float* __restrict__ K,
    const float* __restrict__ V, float* __restrict__ O)
{
    extern __shared__ float sm[];
    const uint32_t sb = smem_u32(sm);
    const int tid = threadIdx.x;
    const int wid = tid >> 5, lane = tid & 31;
    const int g = lane >> 2, q = lane & 3;
    const int bh = blockIdx.y;
    const int q0 = blockIdx.x * 128;

    const float* Qb = Q + (size_t)bh * N_ * D_;
    const float* Kb = K + (size_t)bh * N_ * D_;
    const float* Vb = V + (size_t)bh * N_ * D_;

    // Q tile -> smem (async, one group)
#pragma unroll
    for (int i = 0; i < 8; i++) {
        int c = tid + i * 256;              // 2048 16B chunks
        int row = c >> 4, c4 = c & 15;
        CP16(sb + (uint32_t)(AQ_OFF + row * 68 + c4 * 4) * 4,
             Qb + (size_t)(q0 + row) * D_ + c4 * 4);
    }
    CP_COMMIT();

    auto issueKV = [&](int ck) {
        int s = ck & 1;
        uint32_t kb = sb + (uint32_t)(AK_OFF + s * 64 * 68) * 4;
        uint32_t vb = sb + (uint32_t)(AV_OFF + s * 64 * 72) * 4;
        const float* Kc = Kb + (size_t)ck * 64 * D_;
        const float* Vc = Vb + (size_t)ck * 64 * D_;
#pragma unroll
        for (int i = 0; i < 4; i++) {
            int c = tid + i * 256;          // 1024 chunks each
            int row = c >> 4, c4 = c & 15;
            CP16(kb + (uint32_t)(row * 68 + c4 * 4) * 4,
                 Kc + (size_t)row * D_ + c4 * 4);
            CP16(vb + (uint32_t)(row * 72 + c4 * 4) * 4,
                 Vc + (size_t)row * D_ + c4 * 4);
        }
    };
    issueKV(0); CP_COMMIT();

    // wait for Q (kv0 may still be in flight), load Q fragments (pre-scaled)
    cp_wait<1>();
    __syncthreads();
    uint32_t qf[8][4];
#pragma unroll
    for (int kc = 0; kc < 8; kc++) {
        const float* r0 = sm + AQ_OFF + (wid * 16 + g) * 68 + kc * 8;
        const float* r1 = r0 + 8 * 68;
        qf[kc][0] = f2u(r0[q] * 0.125f);     qf[kc][1] = f2u(r1[q] * 0.125f);
        qf[kc][2] = f2u(r0[q + 4] * 0.125f); qf[kc][3] = f2u(r1[q + 4] * 0.125f);
    }

    float of[8][4];
#pragma unroll
    for (int ni = 0; ni < 8; ni++)
#pragma unroll
        for (int r = 0; r < 4; r++) of[ni][r] = 0.0f;
    float mA = -INFINITY, mB = -INFINITY, lA = 0.0f, lB = 0.0f;

    for (int ck = 0; ck < N_ / 64; ck++) {
        if (ck + 1 < N_ / 64) issueKV(ck + 1);
        CP_COMMIT();
        cp_wait<1>();
        __syncthreads();
        const float* Ksp = sm + AK_OFF + (ck & 1) * 64 * 68;
        const float* Vsp = sm + AV_OFF + (ck & 1) * 64 * 72;

        // S = (Q/8) K^T
        float sf[8][4];
#pragma unroll
        for (int ni = 0; ni < 8; ni++)
#pragma unroll
            for (int r = 0; r < 4; r++) sf[ni][r] = 0.0f;
#pragma unroll
        for (int kc = 0; kc < 8; kc++) {
#pragma unroll
            for (int ni = 0; ni < 8; ni++) {
                const float* rb = Ksp + (ni * 8 + g) * 68 + kc * 8;
                mma8(sf[ni], qf[kc], f2u(rb[q]), f2u(rb[q + 4]));
            }
        }

        // Online softmax (rows rA = wid*16+g, rB = rA+8)
        float mxA = -INFINITY, mxB = -INFINITY;
#pragma unroll
        for (int ni = 0; ni < 8; ni++) {
            mxA = fmaxf(mxA, fmaxf(sf[ni][0], sf[ni][1]));
            mxB = fmaxf(mxB, fmaxf(sf[ni][2], sf[ni][3]));
        }
        mxA = fmaxf(mxA, __shfl_xor_sync(0xffffffffu, mxA, 1));
        mxA = fmaxf(mxA, __shfl_xor_sync(0xffffffffu, mxA, 2));
        mxB = fmaxf(mxB, __shfl_xor_sync(0xffffffffu, mxB, 1));
        mxB = fmaxf(mxB, __shfl_xor_sync(0xffffffffu, mxB, 2));
        float nmA = fmaxf(mA, mxA), nmB = fmaxf(mB, mxB);
        float cA = fexp(mA - nmA), cB = fexp(mB - nmB);
        float suA = 0.0f, suB = 0.0f;
#pragma unroll
        for (int ni = 0; ni < 8; ni++) {
            sf[ni][0] = fexp(sf[ni][0] - nmA);
            sf[ni][1] = fexp(sf[ni][1] - nmA);
            sf[ni][2] = fexp(sf[ni][2] - nmB);
            sf[ni][3] = fexp(sf[ni][3] - nmB);
            suA += sf[ni][0] + sf[ni][1];
            suB += sf[ni][2] + sf[ni][3];
        }
        suA += __shfl_xor_sync(0xffffffffu, suA, 1);
        suA += __shfl_xor_sync(0xffffffffu, suA, 2);
        suB += __shfl_xor_sync(0xffffffffu, suB, 1);
        suB += __shfl_xor_sync(0xffffffffu, suB, 2);
        lA = lA * cA + suA; lB = lB * cB + suB;
        mA = nmA; mB = nmB;
#pragma unroll
        for (int ni = 0; ni < 8; ni++) {
            of[ni][0] *= cA; of[ni][1] *= cA;
            of[ni][2] *= cB; of[ni][3] *= cB;
        }

        // O += P @ V : shuffle-transpose sf[kc] -> A fragment, V from smem
        const int srcl = (lane & 28) | (q >> 1);
        const bool odd = (q & 1);
#pragma unroll
        for (int kc = 0; kc < 8; kc++) {
            float e0 = __shfl_sync(0xffffffffu, sf[kc][0], srcl);
            float o0 = __shfl_sync(0xffffffffu, sf[kc][1], srcl);
            float e1 = __shfl_sync(0xffffffffu, sf[kc][2], srcl);
            float o1 = __shfl_sync(0xffffffffu, sf[kc][3], srcl);
            float e2 = __shfl_sync(0xffffffffu, sf[kc][0], srcl + 2);
            float o2 = __shfl_sync(0xffffffffu, sf[kc][1], srcl + 2);
            float e3 = __shfl_sync(0xffffffffu, sf[kc][2], srcl + 2);
            float o3 = __shfl_sync(0xffffffffu, sf[kc][3], srcl + 2);
            uint32_t a[4];
            a[0] = tf32b(odd ? o0 : e0);
            a[1] = tf32b(odd ? o1 : e1);
            a[2] = tf32b(odd ? o2 : e2);
            a[3] = tf32b(odd ? o3 : e3);
#pragma unroll
            for (int ni = 0; ni < 8; ni++) {
                const float* rb = Vsp + (kc * 8 + q) * 72 + ni * 8 + g;
                mma8(of[ni], a, f2u(rb[0]), f2u(rb[4 * 72]));
            }
        }
        __syncthreads();   // all reads of this K/V buffer done before next issue
    }

    // Epilogue -> AO [b, n, E], tf32-rounded for the output projection
    const int bb = bh / H_, hh = bh - bb * H_;
    float iA = 1.0f / lA, iB = 1.0f / lB;
    int rA = q0 + wid * 16 + g, rB = rA + 8;
#pragma unroll
    for (int ni = 0; ni < 8; ni++) {
        int d0 = ni * 8 + 2 * q;
        float2 vA = make_float2(u2f(tf32b(of[ni][0] * iA)), u2f(tf32b(of[ni][1] * iA)));
        float2 vB = make_float2(u2f(tf32b(of[ni][2] * iB)), u2f(tf32b(of[ni][3] * iB)));
        *(float2*)(O + ((size_t)(bb * N_ + rA)) * E_ + hh * D_ + d0) = vA;
        *(float2*)(O + ((size_t)(bb * N_ + rB)) * E_ + hh * D_ + d0) = vB;
    }
}

// ---------------------------------------------------------------------------
extern "C" void kernel_launch(void* const* d_in, const int* in_sizes, int n_in,
                              void* d_out, int out_size)
{
    const float* x  = (const float*)d_in[0];
    const float* Wq = (const float*)d_in[1];
    const float* bq = (const float*)d_in[2];
    const float* Wk = (const float*)d_in[3];
    const float* bk = (const float*)d_in[4];
    const float* Wv = (const float*)d_in[5];
    const float* bv = (const float*)d_in[6];
    const float* Wo = (const float*)d_in[7];
    const float* bo = (const float*)d_in[8];
    float* out = (float*)d_out;

    float *Qp, *Kp, *Vp, *AOp, *Xr, *Wr;
    cudaGetSymbolAddress((void**)&Qp,  g_Q);
    cudaGetSymbolAddress((void**)&Kp,  g_K);
    cudaGetSymbolAddress((void**)&Vp,  g_V);
    cudaGetSymbolAddress((void**)&AOp, g_AO);
    cudaGetSymbolAddress((void**)&Xr,  g_Xr);
    cudaGetSymbolAddress((void**)&Wr,  g_Wr);

    cudaFuncSetAttribute(tf32_gemm<true>,
                         cudaFuncAttributeMaxDynamicSharedMemorySize, GEMM_SMEM);
    cudaFuncSetAttribute(tf32_gemm<false>,
                         cudaFuncAttributeMaxDynamicSharedMemorySize, GEMM_SMEM);
    cudaFuncSetAttribute(attn_mma,
                         cudaFuncAttributeMaxDynamicSharedMemorySize, ATTN_SMEM);

    // tf32 RN rounding prepass
    {
        int n4x = TOK * E_ / 4, n4w = E_ * E_ / 4;
        round_tf32_kernel<<<(n4x + 255) / 256, 256>>>((const float4*)x, (float4*)Xr, n4x);
        round_tf32_kernel<<<(n4w + 255) / 256, 256>>>((const float4*)Wq, (float4*)(Wr + 0 * (size_t)E_ * E_), n4w);
        round_tf32_kernel<<<(n4w + 255) / 256, 256>>>((const float4*)Wk, (float4*)(Wr + 1 * (size_t)E_ * E_), n4w);
        round_tf32_kernel<<<(n4w + 255) / 256, 256>>>((const float4*)Wv, (float4*)(Wr + 2 * (size_t)E_ * E_), n4w);
        round_tf32_kernel<<<(n4w + 255) / 256, 256>>>((const float4*)Wo, (float4*)(Wr + 3 * (size_t)E_ * E_), n4w);
    }

    // Fused QKV projection
    dim3 gqkv(TOK / 128, 18);
    tf32_gemm<true><<<gqkv, 256, GEMM_SMEM>>>(Xr, Wr, bq, bk, bv, Qp, Kp, Vp);

    // Attention
    dim3 ga(N_ / 128, B_ * H_);
    attn_mma<<<ga, 256, ATTN_SMEM>>>(Qp, Kp, Vp, AOp);

    // Output projection
    dim3 go(TOK / 128, E_ / 128);
    tf32_gemm<false><<<go, 256, GEMM_SMEM>>>(
        AOp, Wr + 3 * (size_t)E_ * E_, bo, bo, bo, out, out, out);
}